// round 8
// baseline (speedup 1.0000x reference)
#include <cuda_runtime.h>
#include <cstdint>

typedef unsigned long long u64;

// ---- packed f32x2 helpers --------------------------------------------------
__device__ __forceinline__ u64 pk2(float a, float b) {
    u64 r; asm("mov.b64 %0, {%1,%2};" : "=l"(r) : "f"(a), "f"(b)); return r;
}
__device__ __forceinline__ void up2(u64 v, float& a, float& b) {
    asm("mov.b64 {%0,%1}, %2;" : "=f"(a), "=f"(b) : "l"(v));
}
__device__ __forceinline__ u64 fma2(u64 a, u64 b, u64 c) {
    u64 d; asm("fma.rn.f32x2 %0, %1, %2, %3;" : "=l"(d) : "l"(a), "l"(b), "l"(c)); return d;
}
__device__ __forceinline__ u64 add2(u64 a, u64 b) {
    u64 d; asm("add.rn.f32x2 %0, %1, %2;" : "=l"(d) : "l"(a), "l"(b)); return d;
}

// ---- problem constants -----------------------------------------------------
constexpr int D      = 64;
constexpr int M      = 2048;
constexpr int K      = 8;
constexpr int NTOK   = 32768;       // B*S
constexpr int PAIRS  = 16;          // token pairs per CTA (tok p, tok p+16)
constexpr int TPC    = 32;          // tokens per CTA
constexpr int CT     = 128;         // codes per tile
constexpr int DS     = 32;          // dims per staged CP slab (d-split)
constexpr int NTILES = M / CT;      // 16
constexpr int NT     = 64;          // threads per CTA (2 warps)
constexpr int NCTA   = NTOK / TPC;  // 1024

// ---- dynamic smem layout (bytes) -------------------------------------------
constexpr int OFF_RP  = 0;                        // u64   RP[D][PAIRS]    8192
constexpr int OFF_CP  = OFF_RP + D * PAIRS * 8;   // float CP[DS][CT]     16384
constexpr int OFF_C2  = OFF_CP + DS * CT * 4;     // float C2[CT]           512
constexpr int OFF_R2  = OFF_C2 + CT * 4;          // u64   R2s[PAIRS]       128
constexpr int OFF_CHO = OFF_R2 + PAIRS * 8;       // int2  CHO[PAIRS]       128
constexpr int SMEMB   = OFF_CHO + PAIRS * 8;      // 25344
constexpr int OFF_MN  = OFF_CP;                   // float4 MN[NT][4] aliases CP

// 64 threads; thread (a = t&3, cg = t>>2) owns pairs {2a,2a+1,2a+8,2a+9}
// x codes {8cg..8cg+7} -> 32 FMA2 accumulators (4x8 block).
// d-split: CP holds 32 dims at a time (2 stagings per tile); the acc chain
// still runs ascending d = 0..63 per (pair, code) -> bit-identical numerics
// (rel_err 0.0 in R1-R6). R7 bug fixed: __syncthreads() after the R2s write
// (R7 read R2s before any barrier -> race -> rel_err 0.34).
__global__ void __launch_bounds__(NT, 6)
rvq_kernel(const float* __restrict__ x, const float* __restrict__ cb,
           float* __restrict__ qout, float* __restrict__ idxout)
{
    extern __shared__ __align__(16) char sm[];
    u64*    RP  = (u64*)(sm + OFF_RP);
    float*  CP  = (float*)(sm + OFF_CP);
    float*  C2  = (float*)(sm + OFF_C2);
    u64*    R2s = (u64*)(sm + OFF_R2);
    int2*   CHO = (int2*)(sm + OFF_CHO);
    float4* MN  = (float4*)(sm + OFF_MN);

    const int t    = threadIdx.x;
    const int base = blockIdx.x * TPC;
    const int pq   = t & 15;        // pair for init/update/output roles
    const int qh   = t >> 4;        // dim quarter (0..3)
    const int tok0 = base + pq;
    const int tok1 = tok0 + PAIRS;
    const int a    = t & 3;         // pair stripe
    const int cg   = t >> 2;        // code group (0..15), 8 codes each

    const u64 NEG1 = pk2(-1.0f, -1.0f);
    const u64 NEG2 = pk2(-2.0f, -2.0f);

    // ---- init: pack x into RP (pair p = tokens p, p+16) ----
    {
        const float4* xa = (const float4*)(x + (size_t)tok0 * D) + qh * 4;
        const float4* xb = (const float4*)(x + (size_t)tok1 * D) + qh * 4;
        #pragma unroll
        for (int i = 0; i < 4; i++) {
            float4 va = xa[i], vb = xb[i];
            int d = qh * 16 + i * 4;
            RP[(d+0)*PAIRS + pq] = pk2(va.x, vb.x);
            RP[(d+1)*PAIRS + pq] = pk2(va.y, vb.y);
            RP[(d+2)*PAIRS + pq] = pk2(va.z, vb.z);
            RP[(d+3)*PAIRS + pq] = pk2(va.w, vb.w);
        }
    }
    __syncthreads();

    for (int k = 0; k < K; k++) {
        const float* cbk = cb + (size_t)k * M * D;

        // ---- r2 per pair: ascending-d packed FMA chain ----
        if (t < PAIRS) {
            u64 n2 = 0ull;
            #pragma unroll 8
            for (int d = 0; d < D; d++) { u64 v = RP[d*PAIRS + t]; n2 = fma2(v, v, n2); }
            R2s[t] = n2;
        }
        __syncthreads();   // R2s visible to all threads (R7's missing barrier)

        float mlo[4], mhi[4]; int ilo[4], ihi[4];
        #pragma unroll
        for (int s = 0; s < 4; s++) {
            mlo[s] = 3.402823466e38f; mhi[s] = 3.402823466e38f; ilo[s] = 0; ihi[s] = 0;
        }

        u64 r2v[4];
        r2v[0] = R2s[2*a];   r2v[1] = R2s[2*a+1];
        r2v[2] = R2s[2*a+8]; r2v[3] = R2s[2*a+9];

        for (int tile = 0; tile < NTILES; tile++) {
            const int c0 = tile * CT + t;           // this thread stages codes c0, c0+64
            const float* r0 = cbk + (size_t)c0 * D;
            const float* r1 = cbk + (size_t)(c0 + 64) * D;
            float c2a0, c2a1;                        // stage-A half-chains (regs)

            u64 acc[4][8];
            #pragma unroll
            for (int p = 0; p < 4; p++)
                #pragma unroll
                for (int c = 0; c < 8; c++) acc[p][c] = 0ull;

            // ================= stage A: dims 0..31 =================
            {
                const float4* s0 = (const float4*)r0;
                const float4* s1 = (const float4*)r1;
                float ca = 0.0f, cc = 0.0f;
                #pragma unroll
                for (int i = 0; i < 8; i++) {       // code c0, dims 0..31
                    float4 v = s0[i]; int d = 4*i;
                    CP[(d+0)*CT + t] = v.x; CP[(d+1)*CT + t] = v.y;
                    CP[(d+2)*CT + t] = v.z; CP[(d+3)*CT + t] = v.w;
                    ca = fmaf(v.x,v.x,ca); ca = fmaf(v.y,v.y,ca);
                    ca = fmaf(v.z,v.z,ca); ca = fmaf(v.w,v.w,ca);
                }
                #pragma unroll
                for (int i = 0; i < 8; i++) {       // code c0+64, dims 0..31
                    float4 v = s1[i]; int d = 4*i;
                    CP[(d+0)*CT + t+64] = v.x; CP[(d+1)*CT + t+64] = v.y;
                    CP[(d+2)*CT + t+64] = v.z; CP[(d+3)*CT + t+64] = v.w;
                    cc = fmaf(v.x,v.x,cc); cc = fmaf(v.y,v.y,cc);
                    cc = fmaf(v.z,v.z,cc); cc = fmaf(v.w,v.w,cc);
                }
                c2a0 = ca; c2a1 = cc;
            }
            __syncthreads();

            // ---- compute A: d = 0..31 ----
            #pragma unroll 4
            for (int d = 0; d < DS; d++) {
                const u64* rp = RP + d * PAIRS;
                ulonglong2 rA = *(const ulonglong2*)(rp + 2*a);
                ulonglong2 rB = *(const ulonglong2*)(rp + 2*a + 8);
                const float4* cf = (const float4*)(CP + d*CT + cg*8);
                float4 cA = cf[0], cB = cf[1];
                u64 cc0 = pk2(cA.x, cA.x), cc1 = pk2(cA.y, cA.y);
                u64 cc2 = pk2(cA.z, cA.z), cc3 = pk2(cA.w, cA.w);
                u64 cc4 = pk2(cB.x, cB.x), cc5 = pk2(cB.y, cB.y);
                u64 cc6 = pk2(cB.z, cB.z), cc7 = pk2(cB.w, cB.w);
                u64 rr[4] = {rA.x, rA.y, rB.x, rB.y};
                #pragma unroll
                for (int p = 0; p < 4; p++) {
                    acc[p][0] = fma2(rr[p], cc0, acc[p][0]);
                    acc[p][1] = fma2(rr[p], cc1, acc[p][1]);
                    acc[p][2] = fma2(rr[p], cc2, acc[p][2]);
                    acc[p][3] = fma2(rr[p], cc3, acc[p][3]);
                    acc[p][4] = fma2(rr[p], cc4, acc[p][4]);
                    acc[p][5] = fma2(rr[p], cc5, acc[p][5]);
                    acc[p][6] = fma2(rr[p], cc6, acc[p][6]);
                    acc[p][7] = fma2(rr[p], cc7, acc[p][7]);
                }
            }
            __syncthreads();

            // ================= stage B: dims 32..63 =================
            {
                const float4* s0 = (const float4*)(r0 + DS);
                const float4* s1 = (const float4*)(r1 + DS);
                float cb2 = 0.0f, cd2 = 0.0f;
                #pragma unroll
                for (int i = 0; i < 8; i++) {       // code c0, dims 32..63
                    float4 v = s0[i]; int d = 4*i;
                    CP[(d+0)*CT + t] = v.x; CP[(d+1)*CT + t] = v.y;
                    CP[(d+2)*CT + t] = v.z; CP[(d+3)*CT + t] = v.w;
                    cb2 = fmaf(v.x,v.x,cb2); cb2 = fmaf(v.y,v.y,cb2);
                    cb2 = fmaf(v.z,v.z,cb2); cb2 = fmaf(v.w,v.w,cb2);
                }
                #pragma unroll
                for (int i = 0; i < 8; i++) {       // code c0+64, dims 32..63
                    float4 v = s1[i]; int d = 4*i;
                    CP[(d+0)*CT + t+64] = v.x; CP[(d+1)*CT + t+64] = v.y;
                    CP[(d+2)*CT + t+64] = v.z; CP[(d+3)*CT + t+64] = v.w;
                    cd2 = fmaf(v.x,v.x,cd2); cd2 = fmaf(v.y,v.y,cd2);
                    cd2 = fmaf(v.z,v.z,cd2); cd2 = fmaf(v.w,v.w,cd2);
                }
                C2[t]    = c2a0 + cb2;               // same two-half c2 sum
                C2[t+64] = c2a1 + cd2;
            }
            __syncthreads();

            // ---- compute B: d = 32..63 (continues the same acc chains) ----
            #pragma unroll 4
            for (int d2i = 0; d2i < DS; d2i++) {
                const u64* rp = RP + (DS + d2i) * PAIRS;
                ulonglong2 rA = *(const ulonglong2*)(rp + 2*a);
                ulonglong2 rB = *(const ulonglong2*)(rp + 2*a + 8);
                const float4* cf = (const float4*)(CP + d2i*CT + cg*8);
                float4 cA = cf[0], cB = cf[1];
                u64 cc0 = pk2(cA.x, cA.x), cc1 = pk2(cA.y, cA.y);
                u64 cc2 = pk2(cA.z, cA.z), cc3 = pk2(cA.w, cA.w);
                u64 cc4 = pk2(cB.x, cB.x), cc5 = pk2(cB.y, cB.y);
                u64 cc6 = pk2(cB.z, cB.z), cc7 = pk2(cB.w, cB.w);
                u64 rr[4] = {rA.x, rA.y, rB.x, rB.y};
                #pragma unroll
                for (int p = 0; p < 4; p++) {
                    acc[p][0] = fma2(rr[p], cc0, acc[p][0]);
                    acc[p][1] = fma2(rr[p], cc1, acc[p][1]);
                    acc[p][2] = fma2(rr[p], cc2, acc[p][2]);
                    acc[p][3] = fma2(rr[p], cc3, acc[p][3]);
                    acc[p][4] = fma2(rr[p], cc4, acc[p][4]);
                    acc[p][5] = fma2(rr[p], cc5, acc[p][5]);
                    acc[p][6] = fma2(rr[p], cc6, acc[p][6]);
                    acc[p][7] = fma2(rr[p], cc7, acc[p][7]);
                }
            }

            // ---- d2 + running argmin (ascending code order per pair) ----
            const int jb = tile * CT + cg * 8;
            #pragma unroll
            for (int c = 0; c < 8; c++) {
                float c2s = C2[cg*8 + c];
                u64 c2dup = pk2(c2s, c2s);
                #pragma unroll
                for (int p = 0; p < 4; p++) {
                    float lo, hi;
                    up2(add2(fma2(acc[p][c], NEG2, r2v[p]), c2dup), lo, hi);
                    if (lo < mlo[p]) { mlo[p] = lo; ilo[p] = jb + c; }
                    if (hi < mhi[p]) { mhi[p] = hi; ihi[p] = jb + c; }
                }
            }
            __syncthreads();   // CP/C2 consumed; next tile may restage
        }

        // ---- cross-thread argmin merge (MN aliases CP) ----
        #pragma unroll
        for (int s = 0; s < 4; s++)
            MN[t*4 + s] = make_float4(mlo[s], __int_as_float(ilo[s]),
                                      mhi[s], __int_as_float(ihi[s]));
        __syncthreads();

        if (t < PAIRS) {
            const int p  = t;
            const int pa = (p & 7) >> 1;             // stripe of pair p
            const int sl = (p >> 3) * 2 + (p & 1);   // slot within stripe
            float g0 = 3.402823466e38f, g1 = g0;
            int gi0 = 0, gi1 = 0;
            #pragma unroll
            for (int c = 0; c < 16; c++) {   // ascending cg = ascending code blocks
                float4 v = MN[(c*4 + pa)*4 + sl];
                float va = v.x, vb = v.z;
                int ia = __float_as_int(v.y), ib = __float_as_int(v.w);
                if (va < g0 || (va == g0 && ia < gi0)) { g0 = va; gi0 = ia; }
                if (vb < g1 || (vb == g1 && ib < gi1)) { g1 = vb; gi1 = ib; }
            }
            CHO[p] = make_int2(gi0, gi1);
            if (idxout) {
                idxout[(size_t)k * NTOK + base + p]         = (float)gi0;
                idxout[(size_t)k * NTOK + base + PAIRS + p] = (float)gi1;
            }
        }
        __syncthreads();

        // ---- residual update: RP[d][p] -= code (exact fma(-1,c,r)) ----
        {
            int2 ch = CHO[pq];
            const float4* ca = (const float4*)(cbk + (size_t)ch.x * D) + qh * 4;
            const float4* cw = (const float4*)(cbk + (size_t)ch.y * D) + qh * 4;
            #pragma unroll
            for (int i = 0; i < 4; i++) {
                float4 u = ca[i], w = cw[i];
                int d = qh * 16 + i * 4;
                RP[(d+0)*PAIRS+pq] = fma2(pk2(u.x, w.x), NEG1, RP[(d+0)*PAIRS+pq]);
                RP[(d+1)*PAIRS+pq] = fma2(pk2(u.y, w.y), NEG1, RP[(d+1)*PAIRS+pq]);
                RP[(d+2)*PAIRS+pq] = fma2(pk2(u.z, w.z), NEG1, RP[(d+2)*PAIRS+pq]);
                RP[(d+3)*PAIRS+pq] = fma2(pk2(u.w, w.w), NEG1, RP[(d+3)*PAIRS+pq]);
            }
        }
        __syncthreads();
    }

    // ---- output: quantized = x - residual (exact elementwise) ----
    {
        const float4* xa = (const float4*)(x + (size_t)tok0 * D) + qh * 4;
        const float4* xb = (const float4*)(x + (size_t)tok1 * D) + qh * 4;
        float4* qa = (float4*)(qout + (size_t)tok0 * D) + qh * 4;
        float4* qb = (float4*)(qout + (size_t)tok1 * D) + qh * 4;
        #pragma unroll
        for (int i = 0; i < 4; i++) {
            float4 va = xa[i], vb = xb[i];
            float4 oa, ob; float lo, hi;
            int d = qh * 16 + i * 4;
            up2(RP[(d+0)*PAIRS+pq], lo, hi); oa.x = va.x - lo; ob.x = vb.x - hi;
            up2(RP[(d+1)*PAIRS+pq], lo, hi); oa.y = va.y - lo; ob.y = vb.y - hi;
            up2(RP[(d+2)*PAIRS+pq], lo, hi); oa.z = va.z - lo; ob.z = vb.z - hi;
            up2(RP[(d+3)*PAIRS+pq], lo, hi); oa.w = va.w - lo; ob.w = vb.w - hi;
            qa[i] = oa; qb[i] = ob;
        }
    }
}

extern "C" void kernel_launch(void* const* d_in, const int* in_sizes, int n_in,
                              void* d_out, int out_size)
{
    const float* x  = (const float*)d_in[0];
    const float* cb = (const float*)d_in[1];
    if (n_in >= 2 && in_sizes[0] == K * M * D && in_sizes[1] == NTOK * D) {
        x  = (const float*)d_in[1];
        cb = (const float*)d_in[0];
    }
    float* q = (float*)d_out;
    float* idxf = (out_size >= NTOK * D + K * NTOK) ? (q + (size_t)NTOK * D) : nullptr;

    cudaFuncSetAttribute(rvq_kernel, cudaFuncAttributeMaxDynamicSharedMemorySize, SMEMB);
    rvq_kernel<<<NCTA, NT, SMEMB>>>(x, cb, q, idxf);
}

// round 9
// speedup vs baseline: 1.0769x; 1.0769x over previous
#include <cuda_runtime.h>
#include <cstdint>

typedef unsigned long long u64;
typedef ulonglong2 u64x2;

// ---- packed f32x2 helpers --------------------------------------------------
__device__ __forceinline__ u64 pk2(float a, float b) {
    u64 r; asm("mov.b64 %0, {%1,%2};" : "=l"(r) : "f"(a), "f"(b)); return r;
}
__device__ __forceinline__ void up2(u64 v, float& a, float& b) {
    asm("mov.b64 {%0,%1}, %2;" : "=f"(a), "=f"(b) : "l"(v));
}
__device__ __forceinline__ u64 fma2(u64 a, u64 b, u64 c) {
    u64 d; asm("fma.rn.f32x2 %0, %1, %2, %3;" : "=l"(d) : "l"(a), "l"(b), "l"(c)); return d;
}
__device__ __forceinline__ u64 add2(u64 a, u64 b) {
    u64 d; asm("add.rn.f32x2 %0, %1, %2;" : "=l"(d) : "l"(a), "l"(b)); return d;
}

// ---- problem constants -----------------------------------------------------
constexpr int D      = 64;
constexpr int M      = 2048;
constexpr int K      = 8;
constexpr int NTOK   = 32768;       // B*S
constexpr int PAIRS  = 16;          // token pairs per CTA (tok p, tok p+16)
constexpr int TPC    = 32;          // tokens per CTA
constexpr int CT     = 128;         // codes per tile
constexpr int DS     = 16;          // dims per staged CP slab
constexpr int NSLAB  = D / DS;      // 4 slabs per tile
constexpr int NTILES = M / CT;      // 16
constexpr int NT     = 32;          // SINGLE-WARP CTA: all barriers = syncwarp
constexpr int NCTA   = NTOK / TPC;  // 1024

// ---- dynamic smem layout (bytes) -------------------------------------------
constexpr int OFF_RP  = 0;                        // u64   RP[D][PAIRS]    8192
constexpr int OFF_CP  = OFF_RP + D * PAIRS * 8;   // float CP[DS][CT]      8192
constexpr int OFF_C2  = OFF_CP + DS * CT * 4;     // float C2[CT]           512
constexpr int OFF_R2  = OFF_C2 + CT * 4;          // u64   R2s[PAIRS]       128
constexpr int OFF_CHO = OFF_R2 + PAIRS * 8;       // int2  CHO[PAIRS]       128
constexpr int SMEMB   = OFF_CHO + PAIRS * 8;      // 17152
constexpr int OFF_MN  = OFF_CP;                   // float4 MN[NT][8] aliases CP

// 32 threads (one warp); thread (a = t&1, cg = t>>1) owns pairs {8a..8a+7}
// x codes {8cg..8cg+7} -> 64 FMA2 accumulators (8x8 block). CP holds 16 dims
// at a time (4 slabs/tile); acc chains run ascending d = 0..63 -> numerics
// bit-identical to R1-R6/R8 (rel_err 0.0): ascending-d FMA chains for
// cross/r2; d2 = (r2 - 2*cross) + c2, c2 = two ascending 32-dim half-chains
// summed (halves carried in registers across slabs); strict-< ascending
// argmin + lexicographic (d2, idx) cross-thread merge.
__global__ void __launch_bounds__(NT, 8)
rvq_kernel(const float* __restrict__ x, const float* __restrict__ cb,
           float* __restrict__ qout, float* __restrict__ idxout)
{
    extern __shared__ __align__(16) char sm[];
    u64*    RP  = (u64*)(sm + OFF_RP);
    float*  CP  = (float*)(sm + OFF_CP);
    float*  C2  = (float*)(sm + OFF_C2);
    u64*    R2s = (u64*)(sm + OFF_R2);
    int2*   CHO = (int2*)(sm + OFF_CHO);
    float4* MN  = (float4*)(sm + OFF_MN);

    const int t    = threadIdx.x;
    const int base = blockIdx.x * TPC;
    const int pq   = t & 15;        // pair for init/update/output roles
    const int qh   = t >> 4;        // dim half (0..1): 32 dims each
    const int tok0 = base + pq;
    const int tok1 = tok0 + PAIRS;
    const int a    = t & 1;         // pair stripe: pairs 8a..8a+7
    const int cg   = t >> 1;        // code group (0..15): codes 8cg..8cg+7

    const u64 NEG1 = pk2(-1.0f, -1.0f);
    const u64 NEG2 = pk2(-2.0f, -2.0f);

    // ---- init: pack x into RP (pair p = tokens p, p+16) ----
    {
        const float4* xa = (const float4*)(x + (size_t)tok0 * D) + qh * 8;
        const float4* xb = (const float4*)(x + (size_t)tok1 * D) + qh * 8;
        #pragma unroll
        for (int i = 0; i < 8; i++) {
            float4 va = xa[i], vb = xb[i];
            int d = qh * 32 + i * 4;
            RP[(d+0)*PAIRS + pq] = pk2(va.x, vb.x);
            RP[(d+1)*PAIRS + pq] = pk2(va.y, vb.y);
            RP[(d+2)*PAIRS + pq] = pk2(va.z, vb.z);
            RP[(d+3)*PAIRS + pq] = pk2(va.w, vb.w);
        }
    }
    __syncwarp();

    for (int k = 0; k < K; k++) {
        const float* cbk = cb + (size_t)k * M * D;

        // ---- r2 per pair: ascending-d packed FMA chain ----
        if (t < PAIRS) {
            u64 n2 = 0ull;
            #pragma unroll 8
            for (int d = 0; d < D; d++) { u64 v = RP[d*PAIRS + t]; n2 = fma2(v, v, n2); }
            R2s[t] = n2;
        }
        __syncwarp();

        float mlo[8], mhi[8]; int ilo[8], ihi[8];
        #pragma unroll
        for (int s = 0; s < 8; s++) {
            mlo[s] = 3.402823466e38f; mhi[s] = 3.402823466e38f; ilo[s] = 0; ihi[s] = 0;
        }

        for (int tile = 0; tile < NTILES; tile++) {
            // this thread stages codes 4t..4t+3 of the tile (all slabs)
            const float* src = cbk + (size_t)(tile * CT + 4 * t) * D;
            float c2r0 = 0.f, c2r1 = 0.f, c2r2 = 0.f, c2r3 = 0.f;  // running chains
            float c2h0 = 0.f, c2h1 = 0.f, c2h2 = 0.f, c2h3 = 0.f;  // saved half A

            u64 acc[8][8];
            #pragma unroll
            for (int p = 0; p < 8; p++)
                #pragma unroll
                for (int c = 0; c < 8; c++) acc[p][c] = 0ull;

            #pragma unroll
            for (int s = 0; s < NSLAB; s++) {
                __syncwarp();   // prior CP consumption complete (compute/eval)

                // ---- stage slab s (dims s*16 .. s*16+15), 4 codes/thread ----
                {
                    const float* sp = src + s * DS;
                    #pragma unroll
                    for (int j = 0; j < 4; j++) {     // dim group 4j..4j+3 in slab
                        float4 v0 = *(const float4*)(sp + 0*D + 4*j);
                        float4 v1 = *(const float4*)(sp + 1*D + 4*j);
                        float4 v2 = *(const float4*)(sp + 2*D + 4*j);
                        float4 v3 = *(const float4*)(sp + 3*D + 4*j);
                        int dd = 4 * j;
                        *(float4*)(CP + (dd+0)*CT + 4*t) = make_float4(v0.x, v1.x, v2.x, v3.x);
                        *(float4*)(CP + (dd+1)*CT + 4*t) = make_float4(v0.y, v1.y, v2.y, v3.y);
                        *(float4*)(CP + (dd+2)*CT + 4*t) = make_float4(v0.z, v1.z, v2.z, v3.z);
                        *(float4*)(CP + (dd+3)*CT + 4*t) = make_float4(v0.w, v1.w, v2.w, v3.w);
                        // c2 chains: per code, ascending dims
                        c2r0 = fmaf(v0.x,v0.x,c2r0); c2r0 = fmaf(v0.y,v0.y,c2r0);
                        c2r0 = fmaf(v0.z,v0.z,c2r0); c2r0 = fmaf(v0.w,v0.w,c2r0);
                        c2r1 = fmaf(v1.x,v1.x,c2r1); c2r1 = fmaf(v1.y,v1.y,c2r1);
                        c2r1 = fmaf(v1.z,v1.z,c2r1); c2r1 = fmaf(v1.w,v1.w,c2r1);
                        c2r2 = fmaf(v2.x,v2.x,c2r2); c2r2 = fmaf(v2.y,v2.y,c2r2);
                        c2r2 = fmaf(v2.z,v2.z,c2r2); c2r2 = fmaf(v2.w,v2.w,c2r2);
                        c2r3 = fmaf(v3.x,v3.x,c2r3); c2r3 = fmaf(v3.y,v3.y,c2r3);
                        c2r3 = fmaf(v3.z,v3.z,c2r3); c2r3 = fmaf(v3.w,v3.w,c2r3);
                    }
                    if (s == 1) {   // end of half A (dims 0..31): save, restart
                        c2h0 = c2r0; c2h1 = c2r1; c2h2 = c2r2; c2h3 = c2r3;
                        c2r0 = 0.f; c2r1 = 0.f; c2r2 = 0.f; c2r3 = 0.f;
                    }
                    if (s == 3) {   // c2 = halfA + halfB (same two-half sum)
                        *(float4*)(C2 + 4*t) =
                            make_float4(c2h0 + c2r0, c2h1 + c2r1,
                                        c2h2 + c2r2, c2h3 + c2r3);
                    }
                }
                __syncwarp();

                // ---- compute slab s: dims s*16..s*16+15, 8x8 block ----
                #pragma unroll 2
                for (int di = 0; di < DS; di++) {
                    const u64* rp = RP + (s * DS + di) * PAIRS + 8 * a;
                    u64x2 rA = *(const u64x2*)(rp + 0);
                    u64x2 rB = *(const u64x2*)(rp + 2);
                    u64x2 rC = *(const u64x2*)(rp + 4);
                    u64x2 rD = *(const u64x2*)(rp + 6);
                    const float4* cf = (const float4*)(CP + di*CT + 8*cg);
                    float4 cA = cf[0], cB = cf[1];
                    u64 cc0 = pk2(cA.x, cA.x), cc1 = pk2(cA.y, cA.y);
                    u64 cc2 = pk2(cA.z, cA.z), cc3 = pk2(cA.w, cA.w);
                    u64 cc4 = pk2(cB.x, cB.x), cc5 = pk2(cB.y, cB.y);
                    u64 cc6 = pk2(cB.z, cB.z), cc7 = pk2(cB.w, cB.w);
                    u64 rr[8] = {rA.x, rA.y, rB.x, rB.y, rC.x, rC.y, rD.x, rD.y};
                    #pragma unroll
                    for (int p = 0; p < 8; p++) {
                        acc[p][0] = fma2(rr[p], cc0, acc[p][0]);
                        acc[p][1] = fma2(rr[p], cc1, acc[p][1]);
                        acc[p][2] = fma2(rr[p], cc2, acc[p][2]);
                        acc[p][3] = fma2(rr[p], cc3, acc[p][3]);
                        acc[p][4] = fma2(rr[p], cc4, acc[p][4]);
                        acc[p][5] = fma2(rr[p], cc5, acc[p][5]);
                        acc[p][6] = fma2(rr[p], cc6, acc[p][6]);
                        acc[p][7] = fma2(rr[p], cc7, acc[p][7]);
                    }
                }
            }

            // ---- d2 + running argmin (ascending code order per pair) ----
            u64 r2v[8];
            {
                const u64x2* rs = (const u64x2*)(R2s + 8*a);
                u64x2 q0 = rs[0], q1 = rs[1], q2 = rs[2], q3 = rs[3];
                r2v[0] = q0.x; r2v[1] = q0.y; r2v[2] = q1.x; r2v[3] = q1.y;
                r2v[4] = q2.x; r2v[5] = q2.y; r2v[6] = q3.x; r2v[7] = q3.y;
            }
            const int jb = tile * CT + cg * 8;
            #pragma unroll
            for (int c = 0; c < 8; c++) {
                float c2s = C2[cg*8 + c];
                u64 c2dup = pk2(c2s, c2s);
                #pragma unroll
                for (int p = 0; p < 8; p++) {
                    float lo, hi;
                    up2(add2(fma2(acc[p][c], NEG2, r2v[p]), c2dup), lo, hi);
                    if (lo < mlo[p]) { mlo[p] = lo; ilo[p] = jb + c; }
                    if (hi < mhi[p]) { mhi[p] = hi; ihi[p] = jb + c; }
                }
            }
        }
        __syncwarp();   // CP consumption done; MN alias safe

        // ---- cross-thread argmin merge (MN aliases CP) ----
        #pragma unroll
        for (int s = 0; s < 8; s++)
            MN[t*8 + s] = make_float4(mlo[s], __int_as_float(ilo[s]),
                                      mhi[s], __int_as_float(ihi[s]));
        __syncwarp();

        if (t < PAIRS) {
            const int p  = t;
            const int pa = p >> 3;      // stripe of pair p
            const int sl = p & 7;       // slot within stripe
            float g0 = 3.402823466e38f, g1 = g0;
            int gi0 = 0, gi1 = 0;
            #pragma unroll
            for (int c = 0; c < 16; c++) {   // ascending cg = ascending code blocks
                float4 v = MN[(2*c + pa)*8 + sl];
                float va = v.x, vb = v.z;
                int ia = __float_as_int(v.y), ib = __float_as_int(v.w);
                if (va < g0 || (va == g0 && ia < gi0)) { g0 = va; gi0 = ia; }
                if (vb < g1 || (vb == g1 && ib < gi1)) { g1 = vb; gi1 = ib; }
            }
            CHO[p] = make_int2(gi0, gi1);
            if (idxout) {
                idxout[(size_t)k * NTOK + base + p]         = (float)gi0;
                idxout[(size_t)k * NTOK + base + PAIRS + p] = (float)gi1;
            }
        }
        __syncwarp();

        // ---- residual update: RP[d][p] -= code (exact fma(-1,c,r)) ----
        {
            int2 ch = CHO[pq];
            const float4* ca = (const float4*)(cbk + (size_t)ch.x * D) + qh * 8;
            const float4* cw = (const float4*)(cbk + (size_t)ch.y * D) + qh * 8;
            #pragma unroll
            for (int i = 0; i < 8; i++) {
                float4 u = ca[i], w = cw[i];
                int d = qh * 32 + i * 4;
                RP[(d+0)*PAIRS+pq] = fma2(pk2(u.x, w.x), NEG1, RP[(d+0)*PAIRS+pq]);
                RP[(d+1)*PAIRS+pq] = fma2(pk2(u.y, w.y), NEG1, RP[(d+1)*PAIRS+pq]);
                RP[(d+2)*PAIRS+pq] = fma2(pk2(u.z, w.z), NEG1, RP[(d+2)*PAIRS+pq]);
                RP[(d+3)*PAIRS+pq] = fma2(pk2(u.w, w.w), NEG1, RP[(d+3)*PAIRS+pq]);
            }
        }
        __syncwarp();
    }

    // ---- output: quantized = x - residual (exact elementwise) ----
    {
        const float4* xa = (const float4*)(x + (size_t)tok0 * D) + qh * 8;
        const float4* xb = (const float4*)(x + (size_t)tok1 * D) + qh * 8;
        float4* qa = (float4*)(qout + (size_t)tok0 * D) + qh * 8;
        float4* qb = (float4*)(qout + (size_t)tok1 * D) + qh * 8;
        #pragma unroll
        for (int i = 0; i < 8; i++) {
            float4 va = xa[i], vb = xb[i];
            float4 oa, ob; float lo, hi;
            int d = qh * 32 + i * 4;
            up2(RP[(d+0)*PAIRS+pq], lo, hi); oa.x = va.x - lo; ob.x = vb.x - hi;
            up2(RP[(d+1)*PAIRS+pq], lo, hi); oa.y = va.y - lo; ob.y = vb.y - hi;
            up2(RP[(d+2)*PAIRS+pq], lo, hi); oa.z = va.z - lo; ob.z = vb.z - hi;
            up2(RP[(d+3)*PAIRS+pq], lo, hi); oa.w = va.w - lo; ob.w = vb.w - hi;
            qa[i] = oa; qb[i] = ob;
        }
    }
}

extern "C" void kernel_launch(void* const* d_in, const int* in_sizes, int n_in,
                              void* d_out, int out_size)
{
    const float* x  = (const float*)d_in[0];
    const float* cb = (const float*)d_in[1];
    if (n_in >= 2 && in_sizes[0] == K * M * D && in_sizes[1] == NTOK * D) {
        x  = (const float*)d_in[1];
        cb = (const float*)d_in[0];
    }
    float* q = (float*)d_out;
    float* idxf = (out_size >= NTOK * D + K * NTOK) ? (q + (size_t)NTOK * D) : nullptr;

    cudaFuncSetAttribute(rvq_kernel, cudaFuncAttributeMaxDynamicSharedMemorySize, SMEMB);
    rvq_kernel<<<NCTA, NT, SMEMB>>>(x, cb, q, idxf);
}

// round 10
// speedup vs baseline: 1.1213x; 1.0412x over previous
#include <cuda_runtime.h>
#include <cstdint>

typedef unsigned long long u64;
typedef ulonglong2 u64x2;

// ---- packed f32x2 helpers --------------------------------------------------
__device__ __forceinline__ u64 pk2(float a, float b) {
    u64 r; asm("mov.b64 %0, {%1,%2};" : "=l"(r) : "f"(a), "f"(b)); return r;
}
__device__ __forceinline__ void up2(u64 v, float& a, float& b) {
    asm("mov.b64 {%0,%1}, %2;" : "=f"(a), "=f"(b) : "l"(v));
}
__device__ __forceinline__ u64 fma2(u64 a, u64 b, u64 c) {
    u64 d; asm("fma.rn.f32x2 %0, %1, %2, %3;" : "=l"(d) : "l"(a), "l"(b), "l"(c)); return d;
}
__device__ __forceinline__ u64 add2(u64 a, u64 b) {
    u64 d; asm("add.rn.f32x2 %0, %1, %2;" : "=l"(d) : "l"(a), "l"(b)); return d;
}

// ---- problem constants -----------------------------------------------------
constexpr int D      = 64;
constexpr int M      = 2048;
constexpr int K      = 8;
constexpr int NTOK   = 32768;       // B*S
constexpr int PAIRS  = 32;          // token pairs per CTA (tok p, tok p+32)
constexpr int TPC    = 64;          // tokens per CTA
constexpr int CT     = 64;          // codes per tile (double-buffered)
constexpr int NTILES = M / CT;      // 32
constexpr int NT     = 64;          // threads per CTA (2 warps)
constexpr int NCTA   = NTOK / TPC;  // 512

// ---- dynamic smem layout (bytes) -------------------------------------------
constexpr int OFF_RP  = 0;                        // u64   RP[D][PAIRS]   16384
constexpr int OFF_CP  = OFF_RP + D * PAIRS * 8;   // float CP[2][D][CT]   32768
constexpr int OFF_C2  = OFF_CP + 2 * D * CT * 4;  // float C2[2][CT]        512
constexpr int OFF_R2  = OFF_C2 + 2 * CT * 4;      // u64   R2s[PAIRS]       256
constexpr int OFF_CHO = OFF_R2 + PAIRS * 8;       // int2  CHO[PAIRS]       256
constexpr int SMEMB   = OFF_CHO + PAIRS * 8;      // 50176
constexpr int OFF_MN  = OFF_CP;                   // float4 MN[NT][4] aliases CP

// 64 threads; thread (a = t&7, cg = t>>3) owns pairs {4a..4a+3} x codes
// {8cg..8cg+7} -> 32 FMA2 accumulators (4x8 block). CP double-buffered:
// LDGs for tile+1 issue before compute of tile; STS lands after compute.
// Numerics bit-identical to all passing rounds (rel_err 0.0 x6):
// ascending-d FMA chains for cross/r2; d2 = (r2 - 2*cross) + c2 with c2 =
// two ascending 32-dim half-chains summed; strict-< ascending argmin +
// lexicographic (d2, idx) cross-thread merge over ascending code blocks.
__global__ void __launch_bounds__(NT, 4)
rvq_kernel(const float* __restrict__ x, const float* __restrict__ cb,
           float* __restrict__ qout, float* __restrict__ idxout)
{
    extern __shared__ __align__(16) char sm[];
    u64*    RP  = (u64*)(sm + OFF_RP);
    float*  CP  = (float*)(sm + OFF_CP);
    float*  C2  = (float*)(sm + OFF_C2);
    u64*    R2s = (u64*)(sm + OFF_R2);
    int2*   CHO = (int2*)(sm + OFF_CHO);
    float4* MN  = (float4*)(sm + OFF_MN);

    const int t    = threadIdx.x;
    const int base = blockIdx.x * TPC;
    const int pq   = t & 31;        // pair for init/update/output roles
    const int qh   = t >> 5;        // dim half (0..1): 32 dims each
    const int tok0 = base + pq;
    const int tok1 = tok0 + PAIRS;
    const int a    = t & 7;         // pair stripe: pairs 4a..4a+3
    const int cg   = t >> 3;        // code group (0..7): codes 8cg..8cg+7

    const u64 NEG1 = pk2(-1.0f, -1.0f);
    const u64 NEG2 = pk2(-2.0f, -2.0f);

    // ---- init: pack x into RP (pair p = tokens p, p+32) ----
    {
        const float4* xa = (const float4*)(x + (size_t)tok0 * D) + qh * 8;
        const float4* xb = (const float4*)(x + (size_t)tok1 * D) + qh * 8;
        #pragma unroll
        for (int i = 0; i < 8; i++) {
            float4 va = xa[i], vb = xb[i];
            int d = qh * 32 + i * 4;
            RP[(d+0)*PAIRS + pq] = pk2(va.x, vb.x);
            RP[(d+1)*PAIRS + pq] = pk2(va.y, vb.y);
            RP[(d+2)*PAIRS + pq] = pk2(va.z, vb.z);
            RP[(d+3)*PAIRS + pq] = pk2(va.w, vb.w);
        }
    }
    __syncthreads();

    for (int k = 0; k < K; k++) {
        const float* cbk = cb + (size_t)k * M * D;

        // ---- r2 per pair: ascending-d packed FMA chain ----
        if (t < PAIRS) {
            u64 n2 = 0ull;
            #pragma unroll 8
            for (int d = 0; d < D; d++) { u64 v = RP[d*PAIRS + t]; n2 = fma2(v, v, n2); }
            R2s[t] = n2;
        }
        __syncthreads();   // R2s visible before any r2v read (R8 fix)

        u64 r2v[4];
        {
            const u64x2* rs = (const u64x2*)(R2s + 4*a);
            u64x2 q0 = rs[0], q1 = rs[1];
            r2v[0] = q0.x; r2v[1] = q0.y; r2v[2] = q1.x; r2v[3] = q1.y;
        }

        float mlo[4], mhi[4]; int ilo[4], ihi[4];
        #pragma unroll
        for (int s = 0; s < 4; s++) {
            mlo[s] = 3.402823466e38f; mhi[s] = 3.402823466e38f; ilo[s] = 0; ihi[s] = 0;
        }

        // ---- prologue: stage tile 0 into buffer 0 (code t of tile) ----
        {
            const float* src = cbk + (size_t)t * D;
            float4 la[8], lb[8];
            #pragma unroll
            for (int i = 0; i < 8; i++) la[i] = *(const float4*)(src + 4*i);
            #pragma unroll
            for (int i = 0; i < 8; i++) lb[i] = *(const float4*)(src + 32 + 4*i);
            float ch = 0.f, cr = 0.f;
            #pragma unroll
            for (int i = 0; i < 8; i++) {
                float4 v = la[i]; int d = 4*i;
                CP[(d+0)*CT + t] = v.x; CP[(d+1)*CT + t] = v.y;
                CP[(d+2)*CT + t] = v.z; CP[(d+3)*CT + t] = v.w;
                ch = fmaf(v.x,v.x,ch); ch = fmaf(v.y,v.y,ch);
                ch = fmaf(v.z,v.z,ch); ch = fmaf(v.w,v.w,ch);
            }
            #pragma unroll
            for (int i = 0; i < 8; i++) {
                float4 v = lb[i]; int d = 32 + 4*i;
                CP[(d+0)*CT + t] = v.x; CP[(d+1)*CT + t] = v.y;
                CP[(d+2)*CT + t] = v.z; CP[(d+3)*CT + t] = v.w;
                cr = fmaf(v.x,v.x,cr); cr = fmaf(v.y,v.y,cr);
                cr = fmaf(v.z,v.z,cr); cr = fmaf(v.w,v.w,cr);
            }
            C2[t] = ch + cr;   // two-half c2 sum
        }
        __syncthreads();

        for (int tile = 0; tile < NTILES; tile++) {
            const int   buf  = tile & 1;
            const int   nbuf = buf ^ 1;
            const float* CPb = CP + buf * (D * CT);
            float*       CPn = CP + nbuf * (D * CT);
            const bool  more = (tile + 1 < NTILES);
            const float* nsrc = cbk + (size_t)((tile + 1) * CT + t) * D;

            u64 acc[4][8];
            #pragma unroll
            for (int p = 0; p < 4; p++)
                #pragma unroll
                for (int c = 0; c < 8; c++) acc[p][c] = 0ull;

            // ---- prefetch chunk A of tile+1 (dims 0..31) ----
            float4 la[8];
            if (more) {
                #pragma unroll
                for (int i = 0; i < 8; i++) la[i] = *(const float4*)(nsrc + 4*i);
            }

            // ---- compute dims 0..31 on CP[buf] ----
            #pragma unroll 4
            for (int d = 0; d < 32; d++) {
                const u64* rp = RP + d * PAIRS + 4*a;
                u64x2 rA = *(const u64x2*)(rp + 0);
                u64x2 rB = *(const u64x2*)(rp + 2);
                const float4* cf = (const float4*)(CPb + d*CT + 8*cg);
                float4 cA = cf[0], cB = cf[1];
                u64 cc0 = pk2(cA.x, cA.x), cc1 = pk2(cA.y, cA.y);
                u64 cc2 = pk2(cA.z, cA.z), cc3 = pk2(cA.w, cA.w);
                u64 cc4 = pk2(cB.x, cB.x), cc5 = pk2(cB.y, cB.y);
                u64 cc6 = pk2(cB.z, cB.z), cc7 = pk2(cB.w, cB.w);
                u64 rr[4] = {rA.x, rA.y, rB.x, rB.y};
                #pragma unroll
                for (int p = 0; p < 4; p++) {
                    acc[p][0] = fma2(rr[p], cc0, acc[p][0]);
                    acc[p][1] = fma2(rr[p], cc1, acc[p][1]);
                    acc[p][2] = fma2(rr[p], cc2, acc[p][2]);
                    acc[p][3] = fma2(rr[p], cc3, acc[p][3]);
                    acc[p][4] = fma2(rr[p], cc4, acc[p][4]);
                    acc[p][5] = fma2(rr[p], cc5, acc[p][5]);
                    acc[p][6] = fma2(rr[p], cc6, acc[p][6]);
                    acc[p][7] = fma2(rr[p], cc7, acc[p][7]);
                }
            }

            // ---- drain chunk A: c2 half + STS into CP[nbuf] ----
            float c2h = 0.f;
            if (more) {
                #pragma unroll
                for (int i = 0; i < 8; i++) {
                    float4 v = la[i]; int d = 4*i;
                    CPn[(d+0)*CT + t] = v.x; CPn[(d+1)*CT + t] = v.y;
                    CPn[(d+2)*CT + t] = v.z; CPn[(d+3)*CT + t] = v.w;
                    c2h = fmaf(v.x,v.x,c2h); c2h = fmaf(v.y,v.y,c2h);
                    c2h = fmaf(v.z,v.z,c2h); c2h = fmaf(v.w,v.w,c2h);
                }
            }

            // ---- prefetch chunk B of tile+1 (dims 32..63) ----
            float4 lb[8];
            if (more) {
                #pragma unroll
                for (int i = 0; i < 8; i++) lb[i] = *(const float4*)(nsrc + 32 + 4*i);
            }

            // ---- compute dims 32..63 on CP[buf] ----
            #pragma unroll 4
            for (int d = 32; d < 64; d++) {
                const u64* rp = RP + d * PAIRS + 4*a;
                u64x2 rA = *(const u64x2*)(rp + 0);
                u64x2 rB = *(const u64x2*)(rp + 2);
                const float4* cf = (const float4*)(CPb + d*CT + 8*cg);
                float4 cA = cf[0], cB = cf[1];
                u64 cc0 = pk2(cA.x, cA.x), cc1 = pk2(cA.y, cA.y);
                u64 cc2 = pk2(cA.z, cA.z), cc3 = pk2(cA.w, cA.w);
                u64 cc4 = pk2(cB.x, cB.x), cc5 = pk2(cB.y, cB.y);
                u64 cc6 = pk2(cB.z, cB.z), cc7 = pk2(cB.w, cB.w);
                u64 rr[4] = {rA.x, rA.y, rB.x, rB.y};
                #pragma unroll
                for (int p = 0; p < 4; p++) {
                    acc[p][0] = fma2(rr[p], cc0, acc[p][0]);
                    acc[p][1] = fma2(rr[p], cc1, acc[p][1]);
                    acc[p][2] = fma2(rr[p], cc2, acc[p][2]);
                    acc[p][3] = fma2(rr[p], cc3, acc[p][3]);
                    acc[p][4] = fma2(rr[p], cc4, acc[p][4]);
                    acc[p][5] = fma2(rr[p], cc5, acc[p][5]);
                    acc[p][6] = fma2(rr[p], cc6, acc[p][6]);
                    acc[p][7] = fma2(rr[p], cc7, acc[p][7]);
                }
            }

            // ---- drain chunk B: c2 half + STS; publish C2[nbuf] ----
            if (more) {
                float c2r = 0.f;
                #pragma unroll
                for (int i = 0; i < 8; i++) {
                    float4 v = lb[i]; int d = 32 + 4*i;
                    CPn[(d+0)*CT + t] = v.x; CPn[(d+1)*CT + t] = v.y;
                    CPn[(d+2)*CT + t] = v.z; CPn[(d+3)*CT + t] = v.w;
                    c2r = fmaf(v.x,v.x,c2r); c2r = fmaf(v.y,v.y,c2r);
                    c2r = fmaf(v.z,v.z,c2r); c2r = fmaf(v.w,v.w,c2r);
                }
                C2[nbuf*CT + t] = c2h + c2r;   // two-half c2 sum
            }

            // ---- d2 + running argmin (ascending code order per pair) ----
            const int jb = tile * CT + cg * 8;
            #pragma unroll
            for (int c = 0; c < 8; c++) {
                float c2s = C2[buf*CT + cg*8 + c];
                u64 c2dup = pk2(c2s, c2s);
                #pragma unroll
                for (int p = 0; p < 4; p++) {
                    float lo, hi;
                    up2(add2(fma2(acc[p][c], NEG2, r2v[p]), c2dup), lo, hi);
                    if (lo < mlo[p]) { mlo[p] = lo; ilo[p] = jb + c; }
                    if (hi < mhi[p]) { mhi[p] = hi; ihi[p] = jb + c; }
                }
            }
            __syncthreads();   // staging of nbuf complete; buf consumed
        }

        // ---- cross-thread argmin merge (MN aliases CP) ----
        #pragma unroll
        for (int s = 0; s < 4; s++)
            MN[t*4 + s] = make_float4(mlo[s], __int_as_float(ilo[s]),
                                      mhi[s], __int_as_float(ihi[s]));
        __syncthreads();

        if (t < PAIRS) {
            const int p  = t;
            const int pa = p >> 2;      // stripe of pair p
            const int sl = p & 3;       // slot within stripe
            float g0 = 3.402823466e38f, g1 = g0;
            int gi0 = 0, gi1 = 0;
            #pragma unroll
            for (int g = 0; g < 8; g++) {   // ascending cg = ascending code blocks
                float4 v = MN[(pa + 8*g)*4 + sl];
                float va = v.x, vb = v.z;
                int ia = __float_as_int(v.y), ib = __float_as_int(v.w);
                if (va < g0 || (va == g0 && ia < gi0)) { g0 = va; gi0 = ia; }
                if (vb < g1 || (vb == g1 && ib < gi1)) { g1 = vb; gi1 = ib; }
            }
            CHO[p] = make_int2(gi0, gi1);
            if (idxout) {
                idxout[(size_t)k * NTOK + base + p]         = (float)gi0;
                idxout[(size_t)k * NTOK + base + PAIRS + p] = (float)gi1;
            }
        }
        __syncthreads();

        // ---- residual update: RP[d][p] -= code (exact fma(-1,c,r)) ----
        {
            int2 ch = CHO[pq];
            const float4* ca = (const float4*)(cbk + (size_t)ch.x * D) + qh * 8;
            const float4* cw = (const float4*)(cbk + (size_t)ch.y * D) + qh * 8;
            #pragma unroll
            for (int i = 0; i < 8; i++) {
                float4 u = ca[i], w = cw[i];
                int d = qh * 32 + i * 4;
                RP[(d+0)*PAIRS+pq] = fma2(pk2(u.x, w.x), NEG1, RP[(d+0)*PAIRS+pq]);
                RP[(d+1)*PAIRS+pq] = fma2(pk2(u.y, w.y), NEG1, RP[(d+1)*PAIRS+pq]);
                RP[(d+2)*PAIRS+pq] = fma2(pk2(u.z, w.z), NEG1, RP[(d+2)*PAIRS+pq]);
                RP[(d+3)*PAIRS+pq] = fma2(pk2(u.w, w.w), NEG1, RP[(d+3)*PAIRS+pq]);
            }
        }
        __syncthreads();
    }

    // ---- output: quantized = x - residual (exact elementwise) ----
    {
        const float4* xa = (const float4*)(x + (size_t)tok0 * D) + qh * 8;
        const float4* xb = (const float4*)(x + (size_t)tok1 * D) + qh * 8;
        float4* qa = (float4*)(qout + (size_t)tok0 * D) + qh * 8;
        float4* qb = (float4*)(qout + (size_t)tok1 * D) + qh * 8;
        #pragma unroll
        for (int i = 0; i < 8; i++) {
            float4 va = xa[i], vb = xb[i];
            float4 oa, ob; float lo, hi;
            int d = qh * 32 + i * 4;
            up2(RP[(d+0)*PAIRS+pq], lo, hi); oa.x = va.x - lo; ob.x = vb.x - hi;
            up2(RP[(d+1)*PAIRS+pq], lo, hi); oa.y = va.y - lo; ob.y = vb.y - hi;
            up2(RP[(d+2)*PAIRS+pq], lo, hi); oa.z = va.z - lo; ob.z = vb.z - hi;
            up2(RP[(d+3)*PAIRS+pq], lo, hi); oa.w = va.w - lo; ob.w = vb.w - hi;
            qa[i] = oa; qb[i] = ob;
        }
    }
}

extern "C" void kernel_launch(void* const* d_in, const int* in_sizes, int n_in,
                              void* d_out, int out_size)
{
    const float* x  = (const float*)d_in[0];
    const float* cb = (const float*)d_in[1];
    if (n_in >= 2 && in_sizes[0] == K * M * D && in_sizes[1] == NTOK * D) {
        x  = (const float*)d_in[1];
        cb = (const float*)d_in[0];
    }
    float* q = (float*)d_out;
    float* idxf = (out_size >= NTOK * D + K * NTOK) ? (q + (size_t)NTOK * D) : nullptr;

    cudaFuncSetAttribute(rvq_kernel, cudaFuncAttributeMaxDynamicSharedMemorySize, SMEMB);
    rvq_kernel<<<NCTA, NT, SMEMB>>>(x, cb, q, idxf);
}

// round 11
// speedup vs baseline: 1.2850x; 1.1461x over previous
#include <cuda_runtime.h>
#include <cstdint>

typedef unsigned long long u64;
typedef ulonglong2 u64x2;

// ---- packed f32x2 helpers --------------------------------------------------
__device__ __forceinline__ u64 pk2(float a, float b) {
    u64 r; asm("mov.b64 %0, {%1,%2};" : "=l"(r) : "f"(a), "f"(b)); return r;
}
__device__ __forceinline__ void up2(u64 v, float& a, float& b) {
    asm("mov.b64 {%0,%1}, %2;" : "=f"(a), "=f"(b) : "l"(v));
}
__device__ __forceinline__ u64 fma2(u64 a, u64 b, u64 c) {
    u64 d; asm("fma.rn.f32x2 %0, %1, %2, %3;" : "=l"(d) : "l"(a), "l"(b), "l"(c)); return d;
}
__device__ __forceinline__ u64 add2(u64 a, u64 b) {
    u64 d; asm("add.rn.f32x2 %0, %1, %2;" : "=l"(d) : "l"(a), "l"(b)); return d;
}

// ---- problem constants -----------------------------------------------------
constexpr int D      = 64;
constexpr int M      = 2048;
constexpr int K      = 8;
constexpr int NTOK   = 32768;       // B*S
constexpr int PAIRS  = 32;          // token pairs per CTA (tok p, tok p+32)
constexpr int TPC    = 64;          // tokens per CTA
constexpr int CT     = 256;         // codes per staged tile (big tile)
constexpr int NTILES = M / CT;      // 8  (half the barriers of R4)
constexpr int NT     = 128;         // threads per CTA (4 warps)
constexpr int NCTA   = NTOK / TPC;  // 512

// ---- dynamic smem layout (bytes) -------------------------------------------
constexpr int OFF_RP  = 0;                        // u64   RP[D][PAIRS]   16384
constexpr int OFF_CP  = OFF_RP + D * PAIRS * 8;   // float CP[D][CT]      65536
constexpr int OFF_C2  = OFF_CP + D * CT * 4;      // float C2[CT]          1024
constexpr int OFF_R2  = OFF_C2 + CT * 4;          // u64   R2s[PAIRS]       256
constexpr int OFF_CHO = OFF_R2 + PAIRS * 8;       // int2  CHO[PAIRS]       256
constexpr int SMEMB   = OFF_CHO + PAIRS * 8;      // 83456 -> 2 CTAs/SM
constexpr int OFF_MN  = OFF_CP;                   // float4 MN[NT][8] aliases CP

// R4's exact thread program at 2x CTA width: 128 threads; thread
// (pb = 2*(t&3), cg = t>>2) owns pairs {pb,pb+1, pb+8,pb+9, pb+16,pb+17,
// pb+24,pb+25} x codes {8cg..8cg+7} -> 64 FMA2 accumulators (8x8 block).
// CP holds plain floats; {c,c} dup in registers. smem 81.5KB -> exactly
// 2 CTAs/SM = 8 warps/SM uniform; NTILES=8 halves barrier count vs R4.
// Numerics bit-identical to all passing rounds (rel_err 0.0 x7):
// ascending-d FMA chains for cross/r2; d2 = (r2 - 2*cross) + c2 with c2 =
// two ascending 32-dim half-chains summed; strict-< ascending argmin +
// lexicographic (d2, idx) cross-thread merge over ascending code blocks.
__global__ void __launch_bounds__(NT, 2)
rvq_kernel(const float* __restrict__ x, const float* __restrict__ cb,
           float* __restrict__ qout, float* __restrict__ idxout)
{
    extern __shared__ __align__(16) char sm[];
    u64*    RP  = (u64*)(sm + OFF_RP);
    float*  CP  = (float*)(sm + OFF_CP);
    float*  C2  = (float*)(sm + OFF_C2);
    u64*    R2s = (u64*)(sm + OFF_R2);
    int2*   CHO = (int2*)(sm + OFF_CHO);
    float4* MN  = (float4*)(sm + OFF_MN);

    const int t    = threadIdx.x;
    const int base = blockIdx.x * TPC;
    const int pq   = t & 31;        // pair for init/update/output roles
    const int qh   = t >> 5;        // dim quarter (0..3): 16 dims each
    const int tok0 = base + pq;
    const int tok1 = tok0 + PAIRS;
    const int pb   = (t & 3) * 2;   // pair base (adjacent pair for LDS.128)
    const int cg   = t >> 2;        // code group (0..31), 8 codes each

    const u64 NEG1 = pk2(-1.0f, -1.0f);
    const u64 NEG2 = pk2(-2.0f, -2.0f);

    // ---- init: pack x into RP (pair p = tokens p, p+32) ----
    {
        const float4* xa = (const float4*)(x + (size_t)tok0 * D) + qh * 4;
        const float4* xb = (const float4*)(x + (size_t)tok1 * D) + qh * 4;
        #pragma unroll
        for (int i = 0; i < 4; i++) {
            float4 va = xa[i], vb = xb[i];
            int d = qh * 16 + i * 4;
            RP[(d+0)*PAIRS + pq] = pk2(va.x, vb.x);
            RP[(d+1)*PAIRS + pq] = pk2(va.y, vb.y);
            RP[(d+2)*PAIRS + pq] = pk2(va.z, vb.z);
            RP[(d+3)*PAIRS + pq] = pk2(va.w, vb.w);
        }
    }
    __syncthreads();

    for (int k = 0; k < K; k++) {
        const float* cbk = cb + (size_t)k * M * D;

        // ---- r2 per pair: ascending-d packed FMA chain ----
        if (t < PAIRS) {
            u64 n2 = 0ull;
            #pragma unroll 8
            for (int d = 0; d < D; d++) { u64 v = RP[d*PAIRS + t]; n2 = fma2(v, v, n2); }
            R2s[t] = n2;
        }
        __syncthreads();   // R2s visible before r2v reads (R8 fix)

        u64 r2v[8];
        {
            u64x2 q0 = *(const u64x2*)(R2s + pb);
            u64x2 q1 = *(const u64x2*)(R2s + pb + 8);
            u64x2 q2 = *(const u64x2*)(R2s + pb + 16);
            u64x2 q3 = *(const u64x2*)(R2s + pb + 24);
            r2v[0] = q0.x; r2v[1] = q0.y; r2v[2] = q1.x; r2v[3] = q1.y;
            r2v[4] = q2.x; r2v[5] = q2.y; r2v[6] = q3.x; r2v[7] = q3.y;
        }

        float mlo[8], mhi[8]; int ilo[8], ihi[8];
        #pragma unroll
        for (int s = 0; s < 8; s++) {
            mlo[s] = 3.402823466e38f; mhi[s] = 3.402823466e38f; ilo[s] = 0; ihi[s] = 0;
        }

        for (int tile = 0; tile < NTILES; tile++) {
            // ---- stage 256 codes (codes 2t, 2t+1); c2 = two half-chains ----
            {
                const int c0 = tile * CT + 2 * t;
                const float4* s0 = (const float4*)(cbk + (size_t)c0 * D);
                float c2a = 0.0f, c2b = 0.0f, c2c = 0.0f, c2d = 0.0f;
                #pragma unroll
                for (int i = 0; i < 8; i++) {          // code 2t, dims 0..31
                    float4 v = s0[i]; int d = 4*i;
                    CP[(d+0)*CT + 2*t] = v.x; CP[(d+1)*CT + 2*t] = v.y;
                    CP[(d+2)*CT + 2*t] = v.z; CP[(d+3)*CT + 2*t] = v.w;
                    c2a = fmaf(v.x,v.x,c2a); c2a = fmaf(v.y,v.y,c2a);
                    c2a = fmaf(v.z,v.z,c2a); c2a = fmaf(v.w,v.w,c2a);
                }
                #pragma unroll
                for (int i = 8; i < 16; i++) {         // code 2t, dims 32..63
                    float4 v = s0[i]; int d = 4*i;
                    CP[(d+0)*CT + 2*t] = v.x; CP[(d+1)*CT + 2*t] = v.y;
                    CP[(d+2)*CT + 2*t] = v.z; CP[(d+3)*CT + 2*t] = v.w;
                    c2b = fmaf(v.x,v.x,c2b); c2b = fmaf(v.y,v.y,c2b);
                    c2b = fmaf(v.z,v.z,c2b); c2b = fmaf(v.w,v.w,c2b);
                }
                const float4* s1 = s0 + 16;            // code 2t+1
                #pragma unroll
                for (int i = 0; i < 8; i++) {
                    float4 v = s1[i]; int d = 4*i;
                    CP[(d+0)*CT + 2*t+1] = v.x; CP[(d+1)*CT + 2*t+1] = v.y;
                    CP[(d+2)*CT + 2*t+1] = v.z; CP[(d+3)*CT + 2*t+1] = v.w;
                    c2c = fmaf(v.x,v.x,c2c); c2c = fmaf(v.y,v.y,c2c);
                    c2c = fmaf(v.z,v.z,c2c); c2c = fmaf(v.w,v.w,c2c);
                }
                #pragma unroll
                for (int i = 8; i < 16; i++) {
                    float4 v = s1[i]; int d = 4*i;
                    CP[(d+0)*CT + 2*t+1] = v.x; CP[(d+1)*CT + 2*t+1] = v.y;
                    CP[(d+2)*CT + 2*t+1] = v.z; CP[(d+3)*CT + 2*t+1] = v.w;
                    c2d = fmaf(v.x,v.x,c2d); c2d = fmaf(v.y,v.y,c2d);
                    c2d = fmaf(v.z,v.z,c2d); c2d = fmaf(v.w,v.w,c2d);
                }
                C2[2*t]   = c2a + c2b;
                C2[2*t+1] = c2c + c2d;
            }
            __syncthreads();

            // ---- cross: 8 pairs x 8 codes per thread, ascending-d chains ----
            u64 acc[8][8];
            #pragma unroll
            for (int p = 0; p < 8; p++)
                #pragma unroll
                for (int c = 0; c < 8; c++) acc[p][c] = 0ull;

            #pragma unroll 2
            for (int d = 0; d < D; d++) {
                const u64* rp = RP + d * PAIRS;
                u64x2 rA = *(const u64x2*)(rp + pb);
                u64x2 rB = *(const u64x2*)(rp + pb + 8);
                u64x2 rC = *(const u64x2*)(rp + pb + 16);
                u64x2 rD = *(const u64x2*)(rp + pb + 24);
                const float4* cf = (const float4*)(CP + d*CT + cg*8);
                float4 cA = cf[0], cB = cf[1];
                u64 cc0 = pk2(cA.x, cA.x), cc1 = pk2(cA.y, cA.y);
                u64 cc2 = pk2(cA.z, cA.z), cc3 = pk2(cA.w, cA.w);
                u64 cc4 = pk2(cB.x, cB.x), cc5 = pk2(cB.y, cB.y);
                u64 cc6 = pk2(cB.z, cB.z), cc7 = pk2(cB.w, cB.w);
                u64 rr[8] = {rA.x, rA.y, rB.x, rB.y, rC.x, rC.y, rD.x, rD.y};
                #pragma unroll
                for (int p = 0; p < 8; p++) {
                    acc[p][0] = fma2(rr[p], cc0, acc[p][0]);
                    acc[p][1] = fma2(rr[p], cc1, acc[p][1]);
                    acc[p][2] = fma2(rr[p], cc2, acc[p][2]);
                    acc[p][3] = fma2(rr[p], cc3, acc[p][3]);
                    acc[p][4] = fma2(rr[p], cc4, acc[p][4]);
                    acc[p][5] = fma2(rr[p], cc5, acc[p][5]);
                    acc[p][6] = fma2(rr[p], cc6, acc[p][6]);
                    acc[p][7] = fma2(rr[p], cc7, acc[p][7]);
                }
            }

            // ---- d2 + running argmin (ascending code order per pair) ----
            const int jb = tile * CT + cg * 8;
            #pragma unroll
            for (int c = 0; c < 8; c++) {
                float c2s = C2[cg*8 + c];
                u64 c2dup = pk2(c2s, c2s);
                #pragma unroll
                for (int p = 0; p < 8; p++) {
                    float lo, hi;
                    up2(add2(fma2(acc[p][c], NEG2, r2v[p]), c2dup), lo, hi);
                    if (lo < mlo[p]) { mlo[p] = lo; ilo[p] = jb + c; }
                    if (hi < mhi[p]) { mhi[p] = hi; ihi[p] = jb + c; }
                }
            }
            __syncthreads();   // CP/C2 consumed; safe to restage / alias MN
        }

        // ---- cross-thread argmin merge (MN aliases CP) ----
        #pragma unroll
        for (int s = 0; s < 8; s++)
            MN[t*8 + s] = make_float4(mlo[s], __int_as_float(ilo[s]),
                                      mhi[s], __int_as_float(ihi[s]));
        __syncthreads();

        if (t < PAIRS) {
            const int p    = t;
            const int pr2  = (p & 7) >> 1;             // stripe of pair p
            const int slot = (p >> 3) * 2 + (p & 1);   // local pair slot
            float g0 = 3.402823466e38f, g1 = g0;
            int gi0 = 0, gi1 = 0;
            #pragma unroll
            for (int c = 0; c < 32; c++) {   // ascending cg = ascending code blocks
                float4 v = MN[(c*4 + pr2)*8 + slot];
                float va = v.x, vb = v.z;
                int ia = __float_as_int(v.y), ib = __float_as_int(v.w);
                if (va < g0 || (va == g0 && ia < gi0)) { g0 = va; gi0 = ia; }
                if (vb < g1 || (vb == g1 && ib < gi1)) { g1 = vb; gi1 = ib; }
            }
            CHO[p] = make_int2(gi0, gi1);
            if (idxout) {
                idxout[(size_t)k * NTOK + base + p]         = (float)gi0;
                idxout[(size_t)k * NTOK + base + PAIRS + p] = (float)gi1;
            }
        }
        __syncthreads();

        // ---- residual update: RP[d][p] -= code (exact fma(-1,c,r)) ----
        {
            int2 ch = CHO[pq];
            const float4* ca = (const float4*)(cbk + (size_t)ch.x * D) + qh * 4;
            const float4* cw = (const float4*)(cbk + (size_t)ch.y * D) + qh * 4;
            #pragma unroll
            for (int i = 0; i < 4; i++) {
                float4 u = ca[i], w = cw[i];
                int d = qh * 16 + i * 4;
                RP[(d+0)*PAIRS+pq] = fma2(pk2(u.x, w.x), NEG1, RP[(d+0)*PAIRS+pq]);
                RP[(d+1)*PAIRS+pq] = fma2(pk2(u.y, w.y), NEG1, RP[(d+1)*PAIRS+pq]);
                RP[(d+2)*PAIRS+pq] = fma2(pk2(u.z, w.z), NEG1, RP[(d+2)*PAIRS+pq]);
                RP[(d+3)*PAIRS+pq] = fma2(pk2(u.w, w.w), NEG1, RP[(d+3)*PAIRS+pq]);
            }
        }
        __syncthreads();
    }

    // ---- output: quantized = x - residual (exact elementwise) ----
    {
        const float4* xa = (const float4*)(x + (size_t)tok0 * D) + qh * 4;
        const float4* xb = (const float4*)(x + (size_t)tok1 * D) + qh * 4;
        float4* qa = (float4*)(qout + (size_t)tok0 * D) + qh * 4;
        float4* qb = (float4*)(qout + (size_t)tok1 * D) + qh * 4;
        #pragma unroll
        for (int i = 0; i < 4; i++) {
            float4 va = xa[i], vb = xb[i];
            float4 oa, ob; float lo, hi;
            int d = qh * 16 + i * 4;
            up2(RP[(d+0)*PAIRS+pq], lo, hi); oa.x = va.x - lo; ob.x = vb.x - hi;
            up2(RP[(d+1)*PAIRS+pq], lo, hi); oa.y = va.y - lo; ob.y = vb.y - hi;
            up2(RP[(d+2)*PAIRS+pq], lo, hi); oa.z = va.z - lo; ob.z = vb.z - hi;
            up2(RP[(d+3)*PAIRS+pq], lo, hi); oa.w = va.w - lo; ob.w = vb.w - hi;
            qa[i] = oa; qb[i] = ob;
        }
    }
}

extern "C" void kernel_launch(void* const* d_in, const int* in_sizes, int n_in,
                              void* d_out, int out_size)
{
    const float* x  = (const float*)d_in[0];
    const float* cb = (const float*)d_in[1];
    if (n_in >= 2 && in_sizes[0] == K * M * D && in_sizes[1] == NTOK * D) {
        x  = (const float*)d_in[1];
        cb = (const float*)d_in[0];
    }
    float* q = (float*)d_out;
    float* idxf = (out_size >= NTOK * D + K * NTOK) ? (q + (size_t)NTOK * D) : nullptr;

    cudaFuncSetAttribute(rvq_kernel, cudaFuncAttributeMaxDynamicSharedMemorySize, SMEMB);
    rvq_kernel<<<NCTA, NT, SMEMB>>>(x, cb, q, idxf);
}